// round 4
// baseline (speedup 1.0000x reference)
#include <cuda_runtime.h>
#include <cuda_bf16.h>
#include <cstdint>
#include <math.h>

// ---------------- problem dims ----------------
#define BATCH 2048
#define TLEN  80
#define EDIM  100
#define UNITS 512
#define DPAD  128              // embedding K padded 100 -> 128
#define KTOT  (UNITS + DPAD)   // 640
#define KC    64               // K chunk (64 bf16 = 128 B row)
#define NCHUNK (KTOT / KC)     // 10
#define BM    128
#define BN    64
#define NCTA  128              // (UNITS/BN) * (BATCH/BM) = 8 * 16

// ---------------- static device scratch ----------------
__device__ __nv_bfloat16 g_Hhi[2][BATCH * UNITS];
__device__ __nv_bfloat16 g_Hlo[2][BATCH * UNITS];
__device__ __nv_bfloat16 g_Xhi[(size_t)TLEN * BATCH * DPAD];
__device__ __nv_bfloat16 g_Xlo[(size_t)TLEN * BATCH * DPAD];
__device__ __nv_bfloat16 g_Wbhi[UNITS * KTOT];   // B-operand layout: [n][k]
__device__ __nv_bfloat16 g_Wblo[UNITS * KTOT];
__device__ unsigned g_bar;                        // grid barrier counter

// ---------------- PTX helpers (arch-agnostic: sm_80-class) ----------------
__device__ __forceinline__ uint32_t smem_to_u32(const void* p) {
    uint32_t a;
    asm("{ .reg .u64 t; cvta.to.shared.u64 t, %1; cvt.u32.u64 %0, t; }" : "=r"(a) : "l"(p));
    return a;
}
#define CP16(dst, src) \
    asm volatile("cp.async.cg.shared.global [%0], [%1], 16;" :: "r"(dst), "l"(src))
#define CP_COMMIT() asm volatile("cp.async.commit_group;" ::: "memory")
#define CP_WAIT(n)  asm volatile("cp.async.wait_group %0;" :: "n"(n) : "memory")

#define LDSM_X4(r0, r1, r2, r3, addr) \
    asm volatile("ldmatrix.sync.aligned.m8n8.x4.shared.b16 {%0,%1,%2,%3}, [%4];" \
                 : "=r"(r0), "=r"(r1), "=r"(r2), "=r"(r3) : "r"(addr))

#define MMA16816(d, a0, a1, a2, a3, b0, b1) \
    asm volatile("mma.sync.aligned.m16n8k16.row.col.f32.bf16.bf16.f32 " \
                 "{%0,%1,%2,%3}, {%4,%5,%6,%7}, {%8,%9}, {%0,%1,%2,%3};" \
                 : "+f"((d)[0]), "+f"((d)[1]), "+f"((d)[2]), "+f"((d)[3]) \
                 : "r"(a0), "r"(a1), "r"(a2), "r"(a3), "r"(b0), "r"(b1))

#define SWZ(bo) ((bo) ^ (((bo) >> 3) & 0x70))

// ---------------- SMEM layout (dynamic) ----------------
// B resident (weight stationary): 2 planes x 10 chunks x 8KB = 163840 B
// A double buffers: 2 bufs x 2 planes x 16KB = 65536 B
// bias: 256 B
#define B_PLANE_SZ  81920
#define B_RES(plane, c) ((plane) * B_PLANE_SZ + (c) * 8192)
#define A_BASE      163840
#define A_OFF(buf, plane) (A_BASE + ((buf) * 2 + (plane)) * 16384)
#define BIAS_OFF    (A_BASE + 65536)                // 229376
#define SMEM_TOTAL  (BIAS_OFF + 256)                // 229632 <= 232448 optin cap

// ---------------- prep kernels ----------------
__global__ void prep_x_kernel(const int* __restrict__ inputs,
                              const float* __restrict__ emb) {
    size_t i = (size_t)blockIdx.x * blockDim.x + threadIdx.x;
    if (i >= (size_t)TLEN * BATCH * DPAD) return;
    int d = (int)(i & (DPAD - 1));
    size_t bt = i >> 7;                 // t*BATCH + b
    int b = (int)(bt & (BATCH - 1));
    int t = (int)(bt >> 11);            // BATCH = 2048 = 2^11
    float x = 0.0f;
    if (d < EDIM) {
        int idx = inputs[(size_t)b * TLEN + t];
        x = emb[(size_t)idx * EDIM + d];
    }
    __nv_bfloat16 hi = __float2bfloat16(x);
    __nv_bfloat16 lo = __float2bfloat16(x - __bfloat162float(hi));
    g_Xhi[i] = hi;
    g_Xlo[i] = lo;
}

__global__ void build_w_kernel(const float* __restrict__ Whh,
                               const float* __restrict__ Wxh) {
    int i = blockIdx.x * blockDim.x + threadIdx.x;
    if (i >= UNITS * KTOT) return;
    int n = i / KTOT;
    int k = i - n * KTOT;
    float v = 0.0f;
    if (k < UNITS)             v = Whh[(size_t)k * UNITS + n];
    else if (k < UNITS + EDIM) v = Wxh[(size_t)(k - UNITS) * UNITS + n];
    __nv_bfloat16 hi = __float2bfloat16(v);
    __nv_bfloat16 lo = __float2bfloat16(v - __bfloat162float(hi));
    g_Wbhi[i] = hi;
    g_Wblo[i] = lo;
}

__global__ void init_h_kernel() {
    int i = blockIdx.x * blockDim.x + threadIdx.x;
    if (i == 0) g_bar = 0u;             // reset grid barrier every launch/replay
    if (i >= BATCH * UNITS) return;
    g_Hhi[0][i] = __float2bfloat16(0.0f);
    g_Hlo[0][i] = __float2bfloat16(0.0f);
}

// ---------------- persistent recurrence kernel ----------------
// All 80 steps inside one kernel. W (hi/lo) resident in SMEM.
// H_next = tanh( [H | X_t] @ Wstack + b_h ), bf16 hi/lo split (3 products).
__global__ __launch_bounds__(512, 1)
void rnn_persistent(const float* __restrict__ bh) {
    extern __shared__ char smem[];
    const uint32_t su  = smem_to_u32(smem);
    const int tid  = threadIdx.x;
    const int wid  = tid >> 5;
    const int lane = tid & 31;
    const int bid  = blockIdx.x;
    const int col0 = (bid & 7) * BN;
    const int row0 = (bid >> 3) * BM;

    // ---- load resident B tiles (both planes, all chunks), swizzled ----
    {
        const __nv_bfloat16* w0 = g_Wbhi + (size_t)col0 * KTOT;
        const __nv_bfloat16* w1 = g_Wblo + (size_t)col0 * KTOT;
#pragma unroll
        for (int i = 0; i < 10; i++) {
            int u  = tid + i * 512;       // 0..5119 (per plane)
            int rg = u >> 3;              // global B row-unit 0..639
            int s  = u & 7;
            int ch = rg >> 6;
            int r  = rg & 63;
            uint32_t so = SWZ((uint32_t)(r * 128 + s * 16));
            const size_t gsrc = (size_t)r * KTOT + ch * 64;
            CP16(su + B_RES(0, ch) + so, (const char*)(w0 + gsrc) + s * 16);
            CP16(su + B_RES(1, ch) + so, (const char*)(w1 + gsrc) + s * 16);
        }
    }
    if (tid < 64) {
        reinterpret_cast<float*>(smem + BIAS_OFF)[tid] = bh[col0 + tid];
    }
    CP_COMMIT();
    CP_WAIT(0);
    __syncthreads();

    // warp tiling: 4 warps M x 4 warps N; warp tile 32(M) x 16(N)
    const int m_base = (wid & 3) * 32;
    const int n_base = (wid >> 2) * 16;
    // ldmatrix lane addressing
    const int a_row = (lane & 15);
    const int a_kh  = (lane >> 4) * 16;              // bytes
    const int b_row = ((lane >> 4) << 3) + (lane & 7);
    const int b_kh  = ((lane >> 3) & 1) * 16;        // bytes

    const float* sbias = reinterpret_cast<const float*>(smem + BIAS_OFF);
    const int g   = lane >> 2;
    const int tig = lane & 3;

    for (int t = 0; t < TLEN; t++) {
        const __nv_bfloat16* __restrict__ Hh = g_Hhi[t & 1];
        const __nv_bfloat16* __restrict__ Hl = g_Hlo[t & 1];
        const __nv_bfloat16* __restrict__ Xh = g_Xhi + (size_t)t * BATCH * DPAD;
        const __nv_bfloat16* __restrict__ Xl = g_Xlo + (size_t)t * BATCH * DPAD;

        auto load_A = [&](int c, int buf) {
            const int k0 = c * KC;
            const __nv_bfloat16 *sh, *sl;
            int stride;
            if (k0 < UNITS) {
                sh = Hh + (size_t)row0 * UNITS + k0;
                sl = Hl + (size_t)row0 * UNITS + k0;
                stride = UNITS;
            } else {
                sh = Xh + (size_t)row0 * DPAD + (k0 - UNITS);
                sl = Xl + (size_t)row0 * DPAD + (k0 - UNITS);
                stride = DPAD;
            }
#pragma unroll
            for (int i = 0; i < 2; i++) {             // 1024 units per plane
                int u = tid + i * 512;
                int r = u >> 3, s = u & 7;
                uint32_t so = SWZ((uint32_t)(r * 128 + s * 16));
                CP16(su + A_OFF(buf, 0) + so, (const char*)(sh + (size_t)r * stride) + s * 16);
                CP16(su + A_OFF(buf, 1) + so, (const char*)(sl + (size_t)r * stride) + s * 16);
            }
            CP_COMMIT();
        };

        float acc[2][2][4];
#pragma unroll
        for (int i = 0; i < 2; i++)
#pragma unroll
            for (int j = 0; j < 2; j++)
#pragma unroll
                for (int q = 0; q < 4; q++) acc[i][j][q] = 0.0f;

        load_A(0, 0);

        for (int c = 0; c < NCHUNK; c++) {
            const int buf = c & 1;
            if (c + 1 < NCHUNK) {
                load_A(c + 1, (c + 1) & 1);
                CP_WAIT(1);
            } else {
                CP_WAIT(0);
            }
            __syncthreads();

            const uint32_t ah  = su + A_OFF(buf, 0);
            const uint32_t al  = su + A_OFF(buf, 1);
            const uint32_t bhp = su + B_RES(0, c);
            const uint32_t blp = su + B_RES(1, c);

#pragma unroll
            for (int ks = 0; ks < 4; ks++) {
                const int kb = ks * 32;               // k byte offset within row

                uint32_t Ahf[2][4], Alf[2][4];
#pragma unroll
                for (int mt = 0; mt < 2; mt++) {
                    uint32_t bo = SWZ((uint32_t)((m_base + mt * 16 + a_row) * 128 + kb + a_kh));
                    LDSM_X4(Ahf[mt][0], Ahf[mt][1], Ahf[mt][2], Ahf[mt][3], ah + bo);
                    LDSM_X4(Alf[mt][0], Alf[mt][1], Alf[mt][2], Alf[mt][3], al + bo);
                }
                uint32_t Bhf[2][2], Blf[2][2];
                {
                    uint32_t bo = SWZ((uint32_t)((n_base + b_row) * 128 + kb + b_kh));
                    LDSM_X4(Bhf[0][0], Bhf[0][1], Bhf[1][0], Bhf[1][1], bhp + bo);
                    LDSM_X4(Blf[0][0], Blf[0][1], Blf[1][0], Blf[1][1], blp + bo);
                }
#pragma unroll
                for (int mt = 0; mt < 2; mt++) {
#pragma unroll
                    for (int nt = 0; nt < 2; nt++) {
                        MMA16816(acc[mt][nt], Ahf[mt][0], Ahf[mt][1], Ahf[mt][2], Ahf[mt][3],
                                 Bhf[nt][0], Bhf[nt][1]);
                        MMA16816(acc[mt][nt], Ahf[mt][0], Ahf[mt][1], Ahf[mt][2], Ahf[mt][3],
                                 Blf[nt][0], Blf[nt][1]);
                        MMA16816(acc[mt][nt], Alf[mt][0], Alf[mt][1], Alf[mt][2], Alf[mt][3],
                                 Bhf[nt][0], Bhf[nt][1]);
                    }
                }
            }
            __syncthreads();
        }

        // ---- epilogue: + b_h, tanh, hi/lo split, store ----
        __nv_bfloat16* __restrict__ dhP = g_Hhi[(t + 1) & 1];
        __nv_bfloat16* __restrict__ dlP = g_Hlo[(t + 1) & 1];
#pragma unroll
        for (int mt = 0; mt < 2; mt++) {
#pragma unroll
            for (int nt = 0; nt < 2; nt++) {
                const int ncol = n_base + nt * 8 + tig * 2;
                const int col  = col0 + ncol;
                const float b0 = sbias[ncol];
                const float b1 = sbias[ncol + 1];
#pragma unroll
                for (int half = 0; half < 2; half++) {
                    const int row = row0 + m_base + mt * 16 + g + half * 8;
                    float v0 = tanhf(acc[mt][nt][half * 2 + 0] + b0);
                    float v1 = tanhf(acc[mt][nt][half * 2 + 1] + b1);
                    __nv_bfloat16 h0 = __float2bfloat16(v0);
                    __nv_bfloat16 h1 = __float2bfloat16(v1);
                    __nv_bfloat16 l0 = __float2bfloat16(v0 - __bfloat162float(h0));
                    __nv_bfloat16 l1 = __float2bfloat16(v1 - __bfloat162float(h1));
                    __nv_bfloat162 hp; hp.x = h0; hp.y = h1;
                    __nv_bfloat162 lp; lp.x = l0; lp.y = l1;
                    *reinterpret_cast<__nv_bfloat162*>(dhP + (size_t)row * UNITS + col) = hp;
                    *reinterpret_cast<__nv_bfloat162*>(dlP + (size_t)row * UNITS + col) = lp;
                }
            }
        }

        // ---- grid barrier (all NCTA CTAs resident: 1 CTA/SM by smem, grid<=SMs) ----
        __syncthreads();
        if (tid == 0) {
            __threadfence();
            atomicAdd(&g_bar, 1u);
            const unsigned target = (unsigned)NCTA * (unsigned)(t + 1);
            while (*(volatile unsigned*)&g_bar < target) { }
            __threadfence();
        }
        __syncthreads();
    }
}

// ---------------- final logits ----------------
__global__ __launch_bounds__(256)
void final_logits_kernel(const float* __restrict__ Wout,
                         const float* __restrict__ bout,
                         float* __restrict__ out) {
    const __nv_bfloat16* __restrict__ hh = g_Hhi[0];  // TLEN=80 even -> plane 0
    const __nv_bfloat16* __restrict__ hl = g_Hlo[0];
    int warp = threadIdx.x >> 5;
    int lane = threadIdx.x & 31;
    int row = blockIdx.x * 8 + warp;
    if (row >= BATCH) return;
    float s = 0.0f;
#pragma unroll
    for (int j = 0; j < UNITS / 32; j++) {
        int k = lane + j * 32;
        float h = __bfloat162float(hh[(size_t)row * UNITS + k]) +
                  __bfloat162float(hl[(size_t)row * UNITS + k]);
        s += h * Wout[k];
    }
#pragma unroll
    for (int o = 16; o; o >>= 1) s += __shfl_xor_sync(0xffffffff, s, o);
    if (lane == 0) out[row] = 1.0f / (1.0f + expf(-(s + bout[0])));
}

// ---------------- launch ----------------
extern "C" void kernel_launch(void* const* d_in, const int* in_sizes, int n_in,
                              void* d_out, int out_size) {
    const int*   inputs = (const int*)  d_in[0];
    const float* emb    = (const float*)d_in[1];
    const float* Wxh    = (const float*)d_in[2];
    const float* Whh    = (const float*)d_in[3];
    const float* bh     = (const float*)d_in[4];
    const float* Wout   = (const float*)d_in[5];
    const float* bout   = (const float*)d_in[6];
    float* out = (float*)d_out;

    cudaFuncSetAttribute(rnn_persistent,
                         cudaFuncAttributeMaxDynamicSharedMemorySize, SMEM_TOTAL);

    {
        size_t n = (size_t)TLEN * BATCH * DPAD;
        prep_x_kernel<<<(unsigned)((n + 255) / 256), 256>>>(inputs, emb);
    }
    build_w_kernel<<<(UNITS * KTOT + 255) / 256, 256>>>(Whh, Wxh);
    init_h_kernel<<<(BATCH * UNITS + 255) / 256, 256>>>();

    rnn_persistent<<<NCTA, 512, SMEM_TOTAL>>>(bh);

    final_logits_kernel<<<BATCH / 8, 256>>>(Wout, bout, out);
}

// round 5
// speedup vs baseline: 1.1734x; 1.1734x over previous
#include <cuda_runtime.h>
#include <cuda_bf16.h>
#include <cstdint>
#include <math.h>

// ---------------- problem dims ----------------
#define BATCH 2048
#define TLEN  80
#define EDIM  100
#define UNITS 512
#define DPAD  128              // embedding K padded 100 -> 128
#define KTOT  (UNITS + DPAD)   // 640
#define KC    64               // K chunk (64 bf16 = 128 B row)
#define NCHUNK (KTOT / KC)     // 10
#define BM    128
#define BN    64
#define NCTA  128              // (UNITS/BN) * (BATCH/BM) = 8 * 16
#define GRPSZ 8                // CTAs per row group (share H rows)

// ---------------- static device scratch ----------------
__device__ __nv_bfloat16 g_Hhi[2][BATCH * UNITS];
__device__ __nv_bfloat16 g_Hlo[2][BATCH * UNITS];
__device__ __nv_bfloat16 g_Xhi[(size_t)TLEN * BATCH * DPAD];
__device__ __nv_bfloat16 g_Xlo[(size_t)TLEN * BATCH * DPAD];
__device__ __nv_bfloat16 g_Wbhi[UNITS * KTOT];   // B-operand layout: [n][k]
__device__ __nv_bfloat16 g_Wblo[UNITS * KTOT];
__device__ unsigned g_gbar[16 * 32];              // per-row-group barrier, 128B stride

// ---------------- PTX helpers (arch-agnostic: sm_80-class) ----------------
__device__ __forceinline__ uint32_t smem_to_u32(const void* p) {
    uint32_t a;
    asm("{ .reg .u64 t; cvta.to.shared.u64 t, %1; cvt.u32.u64 %0, t; }" : "=r"(a) : "l"(p));
    return a;
}
#define CP16(dst, src) \
    asm volatile("cp.async.cg.shared.global [%0], [%1], 16;" :: "r"(dst), "l"(src))
#define CP_COMMIT() asm volatile("cp.async.commit_group;" ::: "memory")
#define CP_WAIT(n)  asm volatile("cp.async.wait_group %0;" :: "n"(n) : "memory")

#define LDSM_X4(r0, r1, r2, r3, addr) \
    asm volatile("ldmatrix.sync.aligned.m8n8.x4.shared.b16 {%0,%1,%2,%3}, [%4];" \
                 : "=r"(r0), "=r"(r1), "=r"(r2), "=r"(r3) : "r"(addr))

#define MMA16816(d, a0, a1, a2, a3, b0, b1) \
    asm volatile("mma.sync.aligned.m16n8k16.row.col.f32.bf16.bf16.f32 " \
                 "{%0,%1,%2,%3}, {%4,%5,%6,%7}, {%8,%9}, {%0,%1,%2,%3};" \
                 : "+f"((d)[0]), "+f"((d)[1]), "+f"((d)[2]), "+f"((d)[3]) \
                 : "r"(a0), "r"(a1), "r"(a2), "r"(a3), "r"(b0), "r"(b1))

#define SWZ(bo) ((bo) ^ (((bo) >> 3) & 0x70))

// ---------------- SMEM layout (dynamic) ----------------
// B resident: 2 planes x 10 chunks x 8KB = 163840 B
// A double buffers: 2 bufs x 2 planes x 16KB = 65536 B ; bias 256 B
#define B_PLANE_SZ  81920
#define B_RES(plane, c) ((plane) * B_PLANE_SZ + (c) * 8192)
#define A_BASE      163840
#define A_OFF(buf, plane) (A_BASE + ((buf) * 2 + (plane)) * 16384)
#define BIAS_OFF    (A_BASE + 65536)                // 229376
#define SMEM_TOTAL  (BIAS_OFF + 256)                // 229632

// ---------------- prep kernels ----------------
__global__ void prep_x_kernel(const int* __restrict__ inputs,
                              const float* __restrict__ emb) {
    size_t i = (size_t)blockIdx.x * blockDim.x + threadIdx.x;
    if (i >= (size_t)TLEN * BATCH * DPAD) return;
    int d = (int)(i & (DPAD - 1));
    size_t bt = i >> 7;
    int b = (int)(bt & (BATCH - 1));
    int t = (int)(bt >> 11);
    float x = 0.0f;
    if (d < EDIM) {
        int idx = inputs[(size_t)b * TLEN + t];
        x = emb[(size_t)idx * EDIM + d];
    }
    __nv_bfloat16 hi = __float2bfloat16(x);
    __nv_bfloat16 lo = __float2bfloat16(x - __bfloat162float(hi));
    g_Xhi[i] = hi;
    g_Xlo[i] = lo;
}

__global__ void build_w_kernel(const float* __restrict__ Whh,
                               const float* __restrict__ Wxh) {
    int i = blockIdx.x * blockDim.x + threadIdx.x;
    if (i >= UNITS * KTOT) return;
    int n = i / KTOT;
    int k = i - n * KTOT;
    float v = 0.0f;
    if (k < UNITS)             v = Whh[(size_t)k * UNITS + n];
    else if (k < UNITS + EDIM) v = Wxh[(size_t)(k - UNITS) * UNITS + n];
    __nv_bfloat16 hi = __float2bfloat16(v);
    __nv_bfloat16 lo = __float2bfloat16(v - __bfloat162float(hi));
    g_Wbhi[i] = hi;
    g_Wblo[i] = lo;
}

__global__ void init_h_kernel() {
    int i = blockIdx.x * blockDim.x + threadIdx.x;
    if (i < 16 * 32) g_gbar[i] = 0u;   // reset all group barriers every replay
    if (i >= BATCH * UNITS) return;
    g_Hhi[0][i] = __float2bfloat16(0.0f);
    g_Hlo[0][i] = __float2bfloat16(0.0f);
}

// ---------------- persistent recurrence kernel ----------------
__global__ __launch_bounds__(512, 1)
void rnn_persistent(const float* __restrict__ bh) {
    extern __shared__ char smem[];
    const uint32_t su  = smem_to_u32(smem);
    const int tid  = threadIdx.x;
    const int wid  = tid >> 5;
    const int lane = tid & 31;
    const int bid  = blockIdx.x;
    const int col0 = (bid & 7) * BN;
    const int row0 = (bid >> 3) * BM;
    const int grp  = bid >> 3;
    volatile unsigned* gbar = &g_gbar[grp * 32];

    // ---- load resident B tiles (both planes, all chunks), swizzled ----
    {
        const __nv_bfloat16* w0 = g_Wbhi + (size_t)col0 * KTOT;
        const __nv_bfloat16* w1 = g_Wblo + (size_t)col0 * KTOT;
#pragma unroll
        for (int i = 0; i < 10; i++) {
            int u  = tid + i * 512;       // 0..5119 per plane
            int rg = u >> 3;
            int s  = u & 7;
            int ch = rg >> 6;
            int r  = rg & 63;
            uint32_t so = SWZ((uint32_t)(r * 128 + s * 16));
            const size_t gsrc = (size_t)r * KTOT + ch * 64;
            CP16(su + B_RES(0, ch) + so, (const char*)(w0 + gsrc) + s * 16);
            CP16(su + B_RES(1, ch) + so, (const char*)(w1 + gsrc) + s * 16);
        }
    }
    if (tid < 64) {
        reinterpret_cast<float*>(smem + BIAS_OFF)[tid] = bh[col0 + tid];
    }
    CP_COMMIT();
    CP_WAIT(0);
    __syncthreads();

    // warp tiling: 4 warps M x 4 warps N; warp tile 32(M) x 16(N)
    const int m_base = (wid & 3) * 32;
    const int n_base = (wid >> 2) * 16;
    const int a_row = (lane & 15);
    const int a_kh  = (lane >> 4) * 16;
    const int b_row = ((lane >> 4) << 3) + (lane & 7);
    const int b_kh  = ((lane >> 3) & 1) * 16;
    const int g   = lane >> 2;
    const int tig = lane & 3;

    // bias values for this thread's accumulator columns
    float binit[2][2];
    {
        const float* sbias = reinterpret_cast<const float*>(smem + BIAS_OFF);
#pragma unroll
        for (int nt = 0; nt < 2; nt++) {
            binit[nt][0] = sbias[n_base + nt * 8 + tig * 2];
            binit[nt][1] = sbias[n_base + nt * 8 + tig * 2 + 1];
        }
    }

    // chunk processing order: X chunks first (no step dependency), then H
    const int ord[NCHUNK] = {8, 9, 0, 1, 2, 3, 4, 5, 6, 7};

    for (int t = 0; t < TLEN; t++) {
        const __nv_bfloat16* __restrict__ Hh = g_Hhi[t & 1];
        const __nv_bfloat16* __restrict__ Hl = g_Hlo[t & 1];
        const __nv_bfloat16* __restrict__ Xh = g_Xhi + (size_t)t * BATCH * DPAD;
        const __nv_bfloat16* __restrict__ Xl = g_Xlo + (size_t)t * BATCH * DPAD;

        auto load_A = [&](int kc, int buf) {
            const __nv_bfloat16 *sh, *sl;
            int stride;
            if (kc < 8) {
                sh = Hh + (size_t)row0 * UNITS + kc * KC;
                sl = Hl + (size_t)row0 * UNITS + kc * KC;
                stride = UNITS;
            } else {
                sh = Xh + (size_t)row0 * DPAD + (kc - 8) * KC;
                sl = Xl + (size_t)row0 * DPAD + (kc - 8) * KC;
                stride = DPAD;
            }
#pragma unroll
            for (int i = 0; i < 2; i++) {
                int u = tid + i * 512;
                int r = u >> 3, s = u & 7;
                uint32_t so = SWZ((uint32_t)(r * 128 + s * 16));
                CP16(su + A_OFF(buf, 0) + so, (const char*)(sh + (size_t)r * stride) + s * 16);
                CP16(su + A_OFF(buf, 1) + so, (const char*)(sl + (size_t)r * stride) + s * 16);
            }
            CP_COMMIT();
        };

        float acc[2][2][4];
#pragma unroll
        for (int mt = 0; mt < 2; mt++)
#pragma unroll
            for (int nt = 0; nt < 2; nt++) {
                acc[mt][nt][0] = binit[nt][0];
                acc[mt][nt][1] = binit[nt][1];
                acc[mt][nt][2] = binit[nt][0];
                acc[mt][nt][3] = binit[nt][1];
            }

        // prologue: issue X chunk loads; overlap barrier spin with their flight
        load_A(ord[0], 0);
        load_A(ord[1], 1);
        if (t > 0) {
            if (tid == 0) {
                const unsigned target = (unsigned)GRPSZ * (unsigned)t;
                while (*gbar < target) { }
                __threadfence();
            }
            __syncthreads();   // gate all warps on barrier passage (H of step t ready)
        }

        // register-resident fragment pipeline (double-buffered over ks)
        uint32_t Ah[2][2][4], Al[2][2][4], Bhf[2][2][2], Blf[2][2][2];

        for (int ci = 0; ci < NCHUNK; ci++) {
            const int kc  = ord[ci];
            const int buf = ci & 1;
            if (ci < NCHUNK - 1) { CP_WAIT(1); } else { CP_WAIT(0); }
            __syncthreads();

            const uint32_t ah  = su + A_OFF(buf, 0);
            const uint32_t al  = su + A_OFF(buf, 1);
            const uint32_t bhp = su + B_RES(0, kc);
            const uint32_t blp = su + B_RES(1, kc);

            // ldsm for ks into pipeline slot pb
#define LDSM_KS(pb, ks) do {                                                      \
                const int kb_ = (ks) * 32;                                        \
                _Pragma("unroll")                                                 \
                for (int mt = 0; mt < 2; mt++) {                                  \
                    uint32_t bo = SWZ((uint32_t)((m_base + mt * 16 + a_row) * 128 \
                                                 + kb_ + a_kh));                  \
                    LDSM_X4(Ah[pb][mt][0], Ah[pb][mt][1],                         \
                            Ah[pb][mt][2], Ah[pb][mt][3], ah + bo);               \
                    LDSM_X4(Al[pb][mt][0], Al[pb][mt][1],                         \
                            Al[pb][mt][2], Al[pb][mt][3], al + bo);               \
                }                                                                 \
                uint32_t bo2 = SWZ((uint32_t)((n_base + b_row) * 128              \
                                              + kb_ + b_kh));                     \
                LDSM_X4(Bhf[pb][0][0], Bhf[pb][0][1],                             \
                        Bhf[pb][1][0], Bhf[pb][1][1], bhp + bo2);                 \
                LDSM_X4(Blf[pb][0][0], Blf[pb][0][1],                             \
                        Blf[pb][1][0], Blf[pb][1][1], blp + bo2);                 \
            } while (0)

#define MMA_KS(pb) do {                                                           \
                _Pragma("unroll")                                                 \
                for (int mt = 0; mt < 2; mt++) {                                  \
                    _Pragma("unroll")                                             \
                    for (int nt = 0; nt < 2; nt++) {                              \
                        MMA16816(acc[mt][nt], Ah[pb][mt][0], Ah[pb][mt][1],       \
                                 Ah[pb][mt][2], Ah[pb][mt][3],                    \
                                 Bhf[pb][nt][0], Bhf[pb][nt][1]);                 \
                        MMA16816(acc[mt][nt], Ah[pb][mt][0], Ah[pb][mt][1],       \
                                 Ah[pb][mt][2], Ah[pb][mt][3],                    \
                                 Blf[pb][nt][0], Blf[pb][nt][1]);                 \
                        MMA16816(acc[mt][nt], Al[pb][mt][0], Al[pb][mt][1],       \
                                 Al[pb][mt][2], Al[pb][mt][3],                    \
                                 Bhf[pb][nt][0], Bhf[pb][nt][1]);                 \
                    }                                                             \
                }                                                                 \
            } while (0)

            LDSM_KS(0, 0);
            LDSM_KS(1, 1);
            MMA_KS(0);
            LDSM_KS(0, 2);
            MMA_KS(1);
            LDSM_KS(1, 3);
            MMA_KS(0);
            MMA_KS(1);

            __syncthreads();
            if (ci + 2 < NCHUNK) load_A(ord[ci + 2], buf);
        }

        // ---- epilogue: tanh, hi/lo split, store ----
        __nv_bfloat16* __restrict__ dhP = g_Hhi[(t + 1) & 1];
        __nv_bfloat16* __restrict__ dlP = g_Hlo[(t + 1) & 1];
#pragma unroll
        for (int mt = 0; mt < 2; mt++) {
#pragma unroll
            for (int nt = 0; nt < 2; nt++) {
                const int col = col0 + n_base + nt * 8 + tig * 2;
#pragma unroll
                for (int half = 0; half < 2; half++) {
                    const int row = row0 + m_base + mt * 16 + g + half * 8;
                    float v0 = tanhf(acc[mt][nt][half * 2 + 0]);
                    float v1 = tanhf(acc[mt][nt][half * 2 + 1]);
                    __nv_bfloat16 h0 = __float2bfloat16(v0);
                    __nv_bfloat16 h1 = __float2bfloat16(v1);
                    __nv_bfloat16 l0 = __float2bfloat16(v0 - __bfloat162float(h0));
                    __nv_bfloat16 l1 = __float2bfloat16(v1 - __bfloat162float(h1));
                    __nv_bfloat162 hp; hp.x = h0; hp.y = h1;
                    __nv_bfloat162 lp; lp.x = l0; lp.y = l1;
                    *reinterpret_cast<__nv_bfloat162*>(dhP + (size_t)row * UNITS + col) = hp;
                    *reinterpret_cast<__nv_bfloat162*>(dlP + (size_t)row * UNITS + col) = lp;
                }
            }
        }

        // ---- group-local arrive (8 CTAs sharing this row block) ----
        __syncthreads();
        if (tid == 0) {
            __threadfence();
            atomicAdd((unsigned*)&g_gbar[grp * 32], 1u);
        }
    }
}

// ---------------- final logits ----------------
__global__ __launch_bounds__(256)
void final_logits_kernel(const float* __restrict__ Wout,
                         const float* __restrict__ bout,
                         float* __restrict__ out) {
    const __nv_bfloat16* __restrict__ hh = g_Hhi[0];  // TLEN=80 even -> plane 0
    const __nv_bfloat16* __restrict__ hl = g_Hlo[0];
    int warp = threadIdx.x >> 5;
    int lane = threadIdx.x & 31;
    int row = blockIdx.x * 8 + warp;
    if (row >= BATCH) return;
    float s = 0.0f;
#pragma unroll
    for (int j = 0; j < UNITS / 32; j++) {
        int k = lane + j * 32;
        float h = __bfloat162float(hh[(size_t)row * UNITS + k]) +
                  __bfloat162float(hl[(size_t)row * UNITS + k]);
        s += h * Wout[k];
    }
#pragma unroll
    for (int o = 16; o; o >>= 1) s += __shfl_xor_sync(0xffffffff, s, o);
    if (lane == 0) out[row] = 1.0f / (1.0f + expf(-(s + bout[0])));
}

// ---------------- launch ----------------
extern "C" void kernel_launch(void* const* d_in, const int* in_sizes, int n_in,
                              void* d_out, int out_size) {
    const int*   inputs = (const int*)  d_in[0];
    const float* emb    = (const float*)d_in[1];
    const float* Wxh    = (const float*)d_in[2];
    const float* Whh    = (const float*)d_in[3];
    const float* bh     = (const float*)d_in[4];
    const float* Wout   = (const float*)d_in[5];
    const float* bout   = (const float*)d_in[6];
    float* out = (float*)d_out;

    cudaFuncSetAttribute(rnn_persistent,
                         cudaFuncAttributeMaxDynamicSharedMemorySize, SMEM_TOTAL);

    {
        size_t n = (size_t)TLEN * BATCH * DPAD;
        prep_x_kernel<<<(unsigned)((n + 255) / 256), 256>>>(inputs, emb);
    }
    build_w_kernel<<<(UNITS * KTOT + 255) / 256, 256>>>(Whh, Wxh);
    init_h_kernel<<<(BATCH * UNITS + 255) / 256, 256>>>();

    rnn_persistent<<<NCTA, 512, SMEM_TOTAL>>>(bh);

    final_logits_kernel<<<BATCH / 8, 256>>>(Wout, bout, out);
}